// round 9
// baseline (speedup 1.0000x reference)
#include <cuda_runtime.h>
#include <math.h>

#define NBATCH 8
#define NPTS   8192
#define NCAND  2048
#define NQ     4
#define NCQ    (NCAND / NQ)            // 512 candidates per quarter
#define NG4Q   (NCQ / 4)               // 128 groups of 4
#define NG8Q   (NCQ / 8)               // 64 groups of 8
#define NTHREADS 512
#define PPT    4
#define PTS_PER_BLOCK (NTHREADS * PPT) // 2048
#define PTBLK  (NPTS / PTS_PER_BLOCK)  // 4 point-blocks per batch
#define NBLOCKS (NBATCH * PTBLK * NQ)  // 128 blocks — all co-resident on 148 SMs

#define BASE_ALPHA 0.05f
#define EPS_F      1e-6f

typedef unsigned long long ull;

// Scratch (allocation-free rule: __device__ globals).
__device__ ull   g_key1[(size_t)NQ * NBATCH * NPTS];
__device__ ull   g_key2[(size_t)NQ * NBATCH * NPTS];
__device__ float g_bm1[NBATCH * PTBLK];
__device__ float g_bm2[NBATCH * PTBLK];
__device__ unsigned g_cnt;   // zero-init; returns to 0 after every barrier
__device__ unsigned g_gen;   // monotonic across barriers and graph replays

// ---- packed fp32x2 helpers (sm_100+; ptxas never emits FFMA2 from C++) ----
__device__ __forceinline__ ull ffma2(ull a, ull b, ull c) {
    ull d;
    asm("fma.rn.f32x2 %0, %1, %2, %3;" : "=l"(d) : "l"(a), "l"(b), "l"(c));
    return d;
}
__device__ __forceinline__ ull pack2(float lo, float hi) {
    ull r;
    asm("mov.b64 %0, {%1, %2};" : "=l"(r) : "f"(lo), "f"(hi));
    return r;
}
__device__ __forceinline__ void unpack2(ull v, float& lo, float& hi) {
    asm("mov.b64 {%0, %1}, %2;" : "=f"(lo), "=f"(hi) : "l"(v));
}

// Ordered key: flipped float score (monotonic as unsigned) || candidate index.
// min(key) == min score; ties -> smaller global index (jnp.argmin first-occurrence).
__device__ __forceinline__ ull make_key(float s, int idx) {
    unsigned int b = __float_as_uint(s);
    b = (b & 0x80000000u) ? ~b : (b | 0x80000000u);
    return ((ull)b << 32) | (unsigned int)idx;
}
__device__ __forceinline__ float key_score(ull k) {
    unsigned int fb = (unsigned int)(k >> 32);
    unsigned int b = (fb & 0x80000000u) ? (fb ^ 0x80000000u) : ~fb;
    return __uint_as_float(b);
}

// Grid-wide barrier: sense counter + generation. Safe because all NBLOCKS (128)
// blocks are co-resident (1 block/SM, 128 <= 148 SMs, launch_bounds below).
__device__ __forceinline__ void grid_barrier() {
    __syncthreads();
    if (threadIdx.x == 0) {
        unsigned g = *((volatile unsigned*)&g_gen);
        __threadfence();                            // release my writes
        unsigned t = atomicAdd(&g_cnt, 1u);
        if (t == NBLOCKS - 1) {
            g_cnt = 0;                              // only last arriver touches cnt
            __threadfence();
            atomicAdd(&g_gen, 1u);
        } else {
            while (*((volatile unsigned*)&g_gen) == g) __nanosleep(64);
        }
        __threadfence();                            // acquire others' writes
    }
    __syncthreads();
}

// min over 4 candidates stored as (xl,xh)(yl,yh)(zl,zh)(hl,hh) packed pairs.
// score = ax*x + (ay*y + (az*z + h)), ax = -px etc. (argmin of 0.5*d^2 - 0.5*|p|^2)
__device__ __forceinline__ float min4(ull ax, ull ay, ull az,
                                      ulonglong2 X, ulonglong2 Y,
                                      ulonglong2 Z, ulonglong2 H) {
    ull tl = ffma2(az, Z.x, H.x);
    tl = ffma2(ay, Y.x, tl);
    tl = ffma2(ax, X.x, tl);
    ull th = ffma2(az, Z.y, H.y);
    th = ffma2(ay, Y.y, th);
    th = ffma2(ax, X.y, th);
    float s0, s1, s2, s3;
    unpack2(tl, s0, s1);
    unpack2(th, s2, s3);
    return fminf(fminf(s0, s1), fminf(s2, s3));
}

// First j in [0,8) of winning group-of-8 with score <= best (scalar FMA chain
// is bitwise-identical to the packed lanes, so an exact match exists).
__device__ __forceinline__ int resolve8(const float* __restrict__ sf,
                                        float ax, float ay, float az, float best) {
    int r = 7;
#pragma unroll
    for (int j = 6; j >= 0; j--) {
        const int q = (j >> 2) * 16, l = j & 3;
        float s = fmaf(ax, sf[q + l],
                  fmaf(ay, sf[q + 4 + l],
                  fmaf(az, sf[q + 8 + l], sf[q + 12 + l])));
        if (s <= best) r = j;
    }
    return r;
}

// Scan this block's candidate quarter for this thread's 4 points.
__device__ __forceinline__ void scan_quarter(const float4* __restrict__ sG,
                                             const float rx[PPT], const float ry[PPT],
                                             const float rz[PPT],
                                             float best[PPT], int gbest[PPT]) {
    ull ax[PPT], ay[PPT], az[PPT];
#pragma unroll
    for (int k = 0; k < PPT; k++) {
        ax[k] = pack2(-rx[k], -rx[k]);
        ay[k] = pack2(-ry[k], -ry[k]);
        az[k] = pack2(-rz[k], -rz[k]);
        best[k] = 3.0e38f;
        gbest[k] = 0;
    }
    const ulonglong2* __restrict__ su = reinterpret_cast<const ulonglong2*>(sG);
#pragma unroll 2
    for (int g = 0; g < NG8Q; g++) {
        ulonglong2 Xa = su[8 * g + 0], Ya = su[8 * g + 1];
        ulonglong2 Za = su[8 * g + 2], Ha = su[8 * g + 3];
        ulonglong2 Xb = su[8 * g + 4], Yb = su[8 * g + 5];
        ulonglong2 Zb = su[8 * g + 6], Hb = su[8 * g + 7];
#pragma unroll
        for (int k = 0; k < PPT; k++) {
            float m = fminf(min4(ax[k], ay[k], az[k], Xa, Ya, Za, Ha),
                            min4(ax[k], ay[k], az[k], Xb, Yb, Zb, Hb));
            if (m < best[k]) { best[k] = m; gbest[k] = g; }  // strict <: first wins
        }
    }
}

__global__ __launch_bounds__(NTHREADS, 1)
void fused_kernel(const float* __restrict__ pred,
                  const float* __restrict__ partial,
                  float* __restrict__ out) {
    __shared__ float4 sG[4 * NG4Q];          // 8 KB: quarter candidates, SoA-by-4 + h
    __shared__ float s_wmax[NTHREADS / 32];

    const int q     = blockIdx.x & (NQ - 1);
    const int ptblk = (blockIdx.x >> 2) & (PTBLK - 1);
    const int b     = blockIdx.x >> 4;

    const float* __restrict__ ppb = partial + (size_t)b * NCAND * 3;
    const float* __restrict__ pq  = ppb + (size_t)q * NCQ * 3;
    const float4* __restrict__ pp4 = (const float4*)pq;

    // Transpose-load quarter: 3 float4 AoS -> 4 float4 SoA (+ h) per group-of-4.
    for (int g = threadIdx.x; g < NG4Q; g += NTHREADS) {
        float4 A = pp4[3 * g + 0];
        float4 B = pp4[3 * g + 1];
        float4 C = pp4[3 * g + 2];
        float4 X = make_float4(A.x, A.w, B.z, C.y);
        float4 Y = make_float4(A.y, B.x, B.w, C.z);
        float4 Z = make_float4(A.z, B.y, C.x, C.w);
        float4 H = make_float4(0.5f * (X.x * X.x + Y.x * Y.x + Z.x * Z.x),
                               0.5f * (X.y * X.y + Y.y * Y.y + Z.y * Z.y),
                               0.5f * (X.z * X.z + Y.z * Y.z + Z.z * Z.z),
                               0.5f * (X.w * X.w + Y.w * Y.w + Z.w * Z.w));
        sG[4 * g + 0] = X;
        sG[4 * g + 1] = Y;
        sG[4 * g + 2] = Z;
        sG[4 * g + 3] = H;
    }
    __syncthreads();

    // This thread's 4 points (coords live in registers for the whole kernel).
    int pidx[PPT];
    float rx[PPT], ry[PPT], rz[PPT];
#pragma unroll
    for (int k = 0; k < PPT; k++) {
        pidx[k] = ptblk * PTS_PER_BLOCK + k * NTHREADS + threadIdx.x;
        const float* pb = pred + ((size_t)b * NPTS + pidx[k]) * 3;
        rx[k] = pb[0]; ry[k] = pb[1]; rz[k] = pb[2];
    }

    const float* sf = (const float*)sG;
    float best[PPT]; int gbest[PPT];
    float d[PPT];    int bi[PPT];

#pragma unroll
    for (int pass = 0; pass < 2; pass++) {
        ull* __restrict__ key = (pass == 0) ? g_key1 : g_key2;
        float* __restrict__ bm = (pass == 0) ? g_bm1 : g_bm2;

        // ---- scan own quarter, publish keys ----
        scan_quarter(sG, rx, ry, rz, best, gbest);
#pragma unroll
        for (int k = 0; k < PPT; k++) {
            int ci = q * NCQ + 8 * gbest[k] +
                     resolve8(sf + 32 * gbest[k], -rx[k], -ry[k], -rz[k], best[k]);
            key[((size_t)q * NBATCH + b) * NPTS + pidx[k]] = make_key(best[k], ci);
        }
        grid_barrier();

        // ---- merge the 4 quarter-keys per point (redundant across siblings) ----
#pragma unroll
        for (int k = 0; k < PPT; k++) {
            const size_t base = (size_t)b * NPTS + pidx[k];
            ull kk = key[base];
#pragma unroll
            for (int qq = 1; qq < NQ; qq++) {
                ull k2 = key[(size_t)qq * NBATCH * NPTS + base];
                if (k2 < kk) kk = k2;
            }
            const float p2 = rx[k] * rx[k] + ry[k] * ry[k] + rz[k] * rz[k];
            d[k]  = sqrtf(fmaxf(fmaf(2.0f, key_score(kk), p2), 0.0f));
            bi[k] = (int)(kk & 0xffffffffu);
        }

        // ---- block max of min_dist; q==0 sibling publishes ----
        float m = fmaxf(fmaxf(d[0], d[1]), fmaxf(d[2], d[3]));
#pragma unroll
        for (int off = 16; off > 0; off >>= 1)
            m = fmaxf(m, __shfl_xor_sync(0xffffffffu, m, off));
        if ((threadIdx.x & 31) == 0) s_wmax[threadIdx.x >> 5] = m;
        __syncthreads();
        if (threadIdx.x == 0 && q == 0) {
            float mm = s_wmax[0];
#pragma unroll
            for (int w = 1; w < NTHREADS / 32; w++) mm = fmaxf(mm, s_wmax[w]);
            bm[b * PTBLK + ptblk] = mm;
        }
        grid_barrier();

        // ---- batch max -> alpha -> update points in registers ----
        float mx = bm[b * PTBLK];
#pragma unroll
        for (int w = 1; w < PTBLK; w++) mx = fmaxf(mx, bm[b * PTBLK + w]);
        const float rbm = 1.0f / (mx + EPS_F);
#pragma unroll
        for (int k = 0; k < PPT; k++) {
            const float a = BASE_ALPHA * (2.0f - d[k] * rbm);
            const float* pc = ppb + 3 * bi[k];
            rx[k] += a * (pc[0] - rx[k]);
            ry[k] += a * (pc[1] - ry[k]);
            rz[k] += a * (pc[2] - rz[k]);
        }
    }

    // q==0 siblings own the output write (all siblings hold identical values).
    if (q == 0) {
#pragma unroll
        for (int k = 0; k < PPT; k++) {
            float* po = out + ((size_t)b * NPTS + pidx[k]) * 3;
            po[0] = rx[k];
            po[1] = ry[k];
            po[2] = rz[k];
        }
    }
}

extern "C" void kernel_launch(void* const* d_in, const int* in_sizes, int n_in,
                              void* d_out, int out_size) {
    const float* pred    = (const float*)d_in[0];   // [8,8192,3]
    const float* partial = (const float*)d_in[1];   // [8,2048,3]
    float* out = (float*)d_out;                     // [8,8192,3]

    fused_kernel<<<NBLOCKS, NTHREADS>>>(pred, partial, out);
}

// round 10
// speedup vs baseline: 1.0283x; 1.0283x over previous
#include <cuda_runtime.h>
#include <math.h>

#define NBATCH 8
#define NPTS   8192
#define NCAND  2048
#define NHALF  2
#define NCH    (NCAND / NHALF)       // 1024 candidates per half
#define NG4H   (NCH / 4)             // 256 groups of 4
#define NG8H   (NCH / 8)             // 128 groups of 8
#define NTHREADS 256
#define PPT    4
#define PTS_PER_BLOCK (NTHREADS * PPT)  // 1024
#define HBLK   (NPTS / PTS_PER_BLOCK)   // 8 point-blocks per batch
#define RBLK   8                         // reduce blocks per batch

#define BASE_ALPHA 0.05f
#define EPS_F      1e-6f

typedef unsigned long long ull;

// Scratch (allocation-free rule: __device__ globals).
__device__ ull   g_key1[(size_t)NHALF * NBATCH * NPTS];
__device__ ull   g_key2[(size_t)NHALF * NBATCH * NPTS];
__device__ float g_rmax1[NBATCH * RBLK];
__device__ float g_rmax2[NBATCH * RBLK];

// ---- packed fp32x2 helpers (sm_100+; ptxas never emits these from C++) ----
__device__ __forceinline__ ull ffma2(ull a, ull b, ull c) {
    ull d;
    asm("fma.rn.f32x2 %0, %1, %2, %3;" : "=l"(d) : "l"(a), "l"(b), "l"(c));
    return d;
}
__device__ __forceinline__ ull fmul2(ull a, ull b) {
    ull d;
    asm("mul.rn.f32x2 %0, %1, %2;" : "=l"(d) : "l"(a), "l"(b));
    return d;
}
__device__ __forceinline__ ull pack2(float lo, float hi) {
    ull r;
    asm("mov.b64 %0, {%1, %2};" : "=l"(r) : "f"(lo), "f"(hi));
    return r;
}
__device__ __forceinline__ void unpack2(ull v, float& lo, float& hi) {
    asm("mov.b64 {%0, %1}, %2;" : "=f"(lo), "=f"(hi) : "l"(v));
}

// Ordered key: flipped float score (monotonic as unsigned) || candidate index.
// min(key) == min score; ties -> smaller global index (jnp.argmin first-occurrence).
__device__ __forceinline__ ull make_key(float s, int idx) {
    unsigned int b = __float_as_uint(s);
    b = (b & 0x80000000u) ? ~b : (b | 0x80000000u);
    return ((ull)b << 32) | (unsigned int)idx;
}
__device__ __forceinline__ float key_score(ull k) {
    unsigned int fb = (unsigned int)(k >> 32);
    unsigned int b = (fb & 0x80000000u) ? (fb ^ 0x80000000u) : ~fb;
    return __uint_as_float(b);
}

__device__ __forceinline__ float max8(const float* __restrict__ a) {
    float m = a[0];
#pragma unroll
    for (int i = 1; i < RBLK; i++) m = fmaxf(m, a[i]);
    return m;
}

// d = sqrt(max(s + |p|^2, 0)) where s = -2 p.c + |c|^2  (== true min distance).
__device__ __forceinline__ float dist_from_key(ull k, float rx, float ry, float rz) {
    const float p2 = fmaf(rx, rx, fmaf(ry, ry, rz * rz));
    return sqrtf(fmaxf(key_score(k) + p2, 0.0f));
}

// Recompute iteration-1 refined point for (b, p). Deterministic & identical
// everywhere it is called (scan2 prologue, reduce2, finalize).
__device__ __forceinline__ void refined1_point(const float* __restrict__ pred,
                                               const float* __restrict__ ppb,
                                               int b, int p, float rbm1,
                                               float& rx, float& ry, float& rz) {
    const float* pb = pred + ((size_t)b * NPTS + p) * 3;
    rx = pb[0]; ry = pb[1]; rz = pb[2];
    const size_t base = (size_t)b * NPTS + p;
    ull k0 = g_key1[base];
    ull k1 = g_key1[(size_t)NBATCH * NPTS + base];
    ull kk = (k1 < k0) ? k1 : k0;
    const float d = dist_from_key(kk, rx, ry, rz);
    const float a = BASE_ALPHA * (2.0f - d * rbm1);
    const float* pc = ppb + 3 * (int)(kk & 0xffffffffu);
    rx += a * (pc[0] - rx);
    ry += a * (pc[1] - ry);
    rz += a * (pc[2] - rz);
}

// First j in [0,8) of the winning group-of-8 with score <= best. The scalar
// chain (incl. h recompute) is bitwise-identical to the packed lanes.
__device__ __forceinline__ int resolve8(const float* __restrict__ xs,
                                        const float* __restrict__ ys,
                                        const float* __restrict__ zs,
                                        float ax, float ay, float az, float best) {
    int r = 7;
#pragma unroll
    for (int j = 6; j >= 0; j--) {
        const float x = xs[j], y = ys[j], z = zs[j];
        const float h = fmaf(x, x, fmaf(y, y, z * z));
        const float s = fmaf(ax, x, fmaf(ay, y, fmaf(az, z, h)));
        if (s <= best) r = j;
    }
    return r;
}

// ITER==1: points = pred. ITER==2: points = refined1 (computed in prologue).
// Each block scans one candidate HALF for 1024 points; publishes 64-bit keys.
template <int ITER>
__global__ __launch_bounds__(NTHREADS, 1)
void scan_kernel(const float* __restrict__ pred,
                 const float* __restrict__ partial) {
    __shared__ float4 sX[NG4H], sY[NG4H], sZ[NG4H];   // 12 KB, SoA-by-4, no H

    const int half = blockIdx.x >> 3;
    const int pblk = blockIdx.x & (HBLK - 1);
    const int b    = blockIdx.y;

    const float* __restrict__ ppb = partial + (size_t)b * NCAND * 3;
    const float4* __restrict__ pp4 = (const float4*)(ppb + (size_t)half * NCH * 3);

    // Transpose load: 3 float4 AoS -> X,Y,Z float4 per group-of-4.
    for (int g = threadIdx.x; g < NG4H; g += NTHREADS) {
        float4 A = pp4[3 * g + 0];   // x0 y0 z0 x1
        float4 B = pp4[3 * g + 1];   // y1 z1 x2 y2
        float4 C = pp4[3 * g + 2];   // z2 x3 y3 z3
        sX[g] = make_float4(A.x, A.w, B.z, C.y);
        sY[g] = make_float4(A.y, B.x, B.w, C.z);
        sZ[g] = make_float4(A.z, B.y, C.x, C.w);
    }
    __syncthreads();

    int   pidx[PPT];
    float rx[PPT], ry[PPT], rz[PPT];
    if (ITER == 1) {
#pragma unroll
        for (int k = 0; k < PPT; k++) {
            pidx[k] = pblk * PTS_PER_BLOCK + k * NTHREADS + threadIdx.x;
            const float* pb = pred + ((size_t)b * NPTS + pidx[k]) * 3;
            rx[k] = pb[0]; ry[k] = pb[1]; rz[k] = pb[2];
        }
    } else {
        const float rbm1 = 1.0f / (max8(g_rmax1 + b * RBLK) + EPS_F);
#pragma unroll
        for (int k = 0; k < PPT; k++) {
            pidx[k] = pblk * PTS_PER_BLOCK + k * NTHREADS + threadIdx.x;
            refined1_point(pred, ppb, b, pidx[k], rbm1, rx[k], ry[k], rz[k]);
        }
    }

    // Packed broadcast coefficients: a = -2p  (score = a.c + |c|^2)
    ull ax[PPT], ay[PPT], az[PPT];
    float best[PPT];
    int gbest[PPT];
#pragma unroll
    for (int k = 0; k < PPT; k++) {
        ax[k] = pack2(-2.0f * rx[k], -2.0f * rx[k]);
        ay[k] = pack2(-2.0f * ry[k], -2.0f * ry[k]);
        az[k] = pack2(-2.0f * rz[k], -2.0f * rz[k]);
        best[k] = 3.0e38f;
        gbest[k] = 0;
    }

    const ulonglong2* __restrict__ uX = (const ulonglong2*)sX;
    const ulonglong2* __restrict__ uY = (const ulonglong2*)sY;
    const ulonglong2* __restrict__ uZ = (const ulonglong2*)sZ;

    for (int g = 0; g < NG8H; g++) {
        // 6 LDS.128 per group-of-8 candidates
        ulonglong2 Xa = uX[2 * g], Xb = uX[2 * g + 1];
        ulonglong2 Ya = uY[2 * g], Yb = uY[2 * g + 1];
        ulonglong2 Za = uZ[2 * g], Zb = uZ[2 * g + 1];

        // h = x*x + (y*y + z*z), packed, shared across all PPT points
        ull hal = ffma2(Xa.x, Xa.x, ffma2(Ya.x, Ya.x, fmul2(Za.x, Za.x)));
        ull hah = ffma2(Xa.y, Xa.y, ffma2(Ya.y, Ya.y, fmul2(Za.y, Za.y)));
        ull hbl = ffma2(Xb.x, Xb.x, ffma2(Yb.x, Yb.x, fmul2(Zb.x, Zb.x)));
        ull hbh = ffma2(Xb.y, Xb.y, ffma2(Yb.y, Yb.y, fmul2(Zb.y, Zb.y)));

#pragma unroll
        for (int k = 0; k < PPT; k++) {
            ull t0 = ffma2(ax[k], Xa.x, ffma2(ay[k], Ya.x, ffma2(az[k], Za.x, hal)));
            ull t1 = ffma2(ax[k], Xa.y, ffma2(ay[k], Ya.y, ffma2(az[k], Za.y, hah)));
            ull t2 = ffma2(ax[k], Xb.x, ffma2(ay[k], Yb.x, ffma2(az[k], Zb.x, hbl)));
            ull t3 = ffma2(ax[k], Xb.y, ffma2(ay[k], Yb.y, ffma2(az[k], Zb.y, hbh)));
            float s0, s1, s2, s3, s4, s5, s6, s7;
            unpack2(t0, s0, s1);
            unpack2(t1, s2, s3);
            unpack2(t2, s4, s5);
            unpack2(t3, s6, s7);
            float m = fminf(fminf(fminf(s0, s1), fminf(s2, s3)),
                            fminf(fminf(s4, s5), fminf(s6, s7)));
            if (m < best[k]) { best[k] = m; gbest[k] = g; }  // strict <: first wins
        }
    }

    ull* __restrict__ key = ((ITER == 1) ? g_key1 : g_key2)
                            + (size_t)half * NBATCH * NPTS;
    const float* fX = (const float*)sX;
    const float* fY = (const float*)sY;
    const float* fZ = (const float*)sZ;
#pragma unroll
    for (int k = 0; k < PPT; k++) {
        const int gq = 8 * gbest[k];
        const int ci = half * NCH + gq +
                       resolve8(fX + gq, fY + gq, fZ + gq,
                                -2.0f * rx[k], -2.0f * ry[k], -2.0f * rz[k], best[k]);
        key[(size_t)b * NPTS + pidx[k]] = make_key(best[k], ci);
    }
}

// Per-block partial max of merged min-distances. 64 blocks; slot = b*RBLK+local.
template <int SET>
__global__ __launch_bounds__(NTHREADS)
void reduce_kernel(const float* __restrict__ pred,
                   const float* __restrict__ partial) {
    __shared__ float s_wmax[NTHREADS / 32];
    const int b  = blockIdx.x >> 3;
    const int lb = blockIdx.x & (RBLK - 1);
    const float* __restrict__ ppb = partial + (size_t)b * NCAND * 3;
    const ull* __restrict__ key = (SET == 1) ? g_key1 : g_key2;

    float rbm1 = 0.0f;
    if (SET == 2) rbm1 = 1.0f / (max8(g_rmax1 + b * RBLK) + EPS_F);

    float mx = 0.0f;
#pragma unroll
    for (int k = 0; k < PPT; k++) {
        const int p = lb * PTS_PER_BLOCK + k * NTHREADS + threadIdx.x;
        float rx, ry, rz;
        if (SET == 1) {
            const float* pb = pred + ((size_t)b * NPTS + p) * 3;
            rx = pb[0]; ry = pb[1]; rz = pb[2];
        } else {
            refined1_point(pred, ppb, b, p, rbm1, rx, ry, rz);
        }
        const size_t base = (size_t)b * NPTS + p;
        ull k0 = key[base];
        ull k1 = key[(size_t)NBATCH * NPTS + base];
        ull kk = (k1 < k0) ? k1 : k0;
        mx = fmaxf(mx, dist_from_key(kk, rx, ry, rz));
    }
#pragma unroll
    for (int off = 16; off > 0; off >>= 1)
        mx = fmaxf(mx, __shfl_xor_sync(0xffffffffu, mx, off));
    if ((threadIdx.x & 31) == 0) s_wmax[threadIdx.x >> 5] = mx;
    __syncthreads();
    if (threadIdx.x == 0) {
        float mm = s_wmax[0];
#pragma unroll
        for (int w = 1; w < NTHREADS / 32; w++) mm = fmaxf(mm, s_wmax[w]);
        ((SET == 1) ? g_rmax1 : g_rmax2)[blockIdx.x] = mm;
    }
}

// refined1 -> apply update 2 -> out.
__global__ __launch_bounds__(NTHREADS)
void finalize_kernel(const float* __restrict__ pred,
                     const float* __restrict__ partial,
                     float* __restrict__ out) {
    const int b  = blockIdx.x >> 3;
    const int lb = blockIdx.x & (RBLK - 1);
    const float* __restrict__ ppb = partial + (size_t)b * NCAND * 3;

    const float rbm1 = 1.0f / (max8(g_rmax1 + b * RBLK) + EPS_F);
    const float rbm2 = 1.0f / (max8(g_rmax2 + b * RBLK) + EPS_F);

#pragma unroll
    for (int k = 0; k < PPT; k++) {
        const int p = lb * PTS_PER_BLOCK + k * NTHREADS + threadIdx.x;
        float rx, ry, rz;
        refined1_point(pred, ppb, b, p, rbm1, rx, ry, rz);

        const size_t base = (size_t)b * NPTS + p;
        ull k0 = g_key2[base];
        ull k1 = g_key2[(size_t)NBATCH * NPTS + base];
        ull kk = (k1 < k0) ? k1 : k0;
        const float d = dist_from_key(kk, rx, ry, rz);
        const float a = BASE_ALPHA * (2.0f - d * rbm2);
        const float* pc = ppb + 3 * (int)(kk & 0xffffffffu);
        rx += a * (pc[0] - rx);
        ry += a * (pc[1] - ry);
        rz += a * (pc[2] - rz);

        float* po = out + ((size_t)b * NPTS + p) * 3;
        po[0] = rx;
        po[1] = ry;
        po[2] = rz;
    }
}

extern "C" void kernel_launch(void* const* d_in, const int* in_sizes, int n_in,
                              void* d_out, int out_size) {
    const float* pred    = (const float*)d_in[0];   // [8,8192,3]
    const float* partial = (const float*)d_in[1];   // [8,2048,3]
    float* out = (float*)d_out;                     // [8,8192,3]

    const dim3 sgrid(NHALF * HBLK, NBATCH);   // 128 scan blocks, 1/SM
    const int  rgrid = NBATCH * RBLK;         // 64 reduce/finalize blocks

    scan_kernel<1><<<sgrid, NTHREADS>>>(pred, partial);
    reduce_kernel<1><<<rgrid, NTHREADS>>>(pred, partial);
    scan_kernel<2><<<sgrid, NTHREADS>>>(pred, partial);
    reduce_kernel<2><<<rgrid, NTHREADS>>>(pred, partial);
    finalize_kernel<<<rgrid, NTHREADS>>>(pred, partial, out);
}

// round 13
// speedup vs baseline: 1.0904x; 1.0604x over previous
#include <cuda_runtime.h>
#include <math.h>

#define NBATCH 8
#define NPTS   8192
#define NCAND  2048
#define NHALF  2
#define NCH    (NCAND / NHALF)       // 1024 candidates per half
#define NG4H   (NCH / 4)             // 256 groups of 4
#define NG8H   (NCH / 8)             // 128 groups of 8
#define NTHREADS 256
#define PPT    4
#define PTS_PER_BLOCK (NTHREADS * PPT)  // 1024
#define HBLK   (NPTS / PTS_PER_BLOCK)   // 8 point-groups per batch

#define BASE_ALPHA 0.05f
#define EPS_F      1e-6f

typedef unsigned long long ull;

// Scratch (allocation-free rule: __device__ globals; all zero-init is benign:
// ikey arrays use inverted keys (0 == +inf identity for atomicMax) and replays
// recompute identical values; counters are reset by their consumer each pass).
__device__ ull      g_ikey1[(size_t)NBATCH * NPTS];
__device__ ull      g_ikey2[(size_t)NBATCH * NPTS];
__device__ float    g_ref1[(size_t)NBATCH * NPTS * 3];
__device__ float    g_rmax1[NBATCH * HBLK];
__device__ float    g_rmax2[NBATCH * HBLK];
__device__ unsigned g_c1[NBATCH * HBLK];
__device__ unsigned g_c2[NBATCH * HBLK];

// ---- packed fp32x2 helpers (sm_100+; ptxas never emits these from C++) ----
__device__ __forceinline__ ull ffma2(ull a, ull b, ull c) {
    ull d;
    asm("fma.rn.f32x2 %0, %1, %2, %3;" : "=l"(d) : "l"(a), "l"(b), "l"(c));
    return d;
}
__device__ __forceinline__ ull fmul2(ull a, ull b) {
    ull d;
    asm("mul.rn.f32x2 %0, %1, %2;" : "=l"(d) : "l"(a), "l"(b));
    return d;
}
__device__ __forceinline__ ull pack2(float lo, float hi) {
    ull r;
    asm("mov.b64 %0, {%1, %2};" : "=l"(r) : "f"(lo), "f"(hi));
    return r;
}
__device__ __forceinline__ void unpack2(ull v, float& lo, float& hi) {
    asm("mov.b64 {%0, %1}, %2;" : "=f"(lo), "=f"(hi) : "l"(v));
}

// Ordered key: flipped float score (monotonic as unsigned) || candidate index.
// min(okey) == min score; ties -> smaller global index (jnp.argmin semantics).
// Stored INVERTED (ikey = ~okey) so atomicMax with zero-init state works.
__device__ __forceinline__ ull make_ikey(float s, int idx) {
    unsigned int b = __float_as_uint(s);
    b = (b & 0x80000000u) ? ~b : (b | 0x80000000u);
    return ~(((ull)b << 32) | (unsigned int)idx);
}
__device__ __forceinline__ float ikey_score(ull ik) {
    unsigned int fb = (unsigned int)((~ik) >> 32);
    unsigned int b = (fb & 0x80000000u) ? (fb ^ 0x80000000u) : ~fb;
    return __uint_as_float(b);
}
__device__ __forceinline__ int ikey_idx(ull ik) {
    return (int)((~ik) & 0xffffffffu);
}

__device__ __forceinline__ float max8(const float* __restrict__ a) {
    float m = a[0];
#pragma unroll
    for (int i = 1; i < HBLK; i++) m = fmaxf(m, a[i]);
    return m;
}

// d = sqrt(max(s + |p|^2, 0)) where s = -2 p.c + |c|^2  (true min distance).
__device__ __forceinline__ float dist_from_ikey(ull ik, float rx, float ry, float rz) {
    const float p2 = fmaf(rx, rx, fmaf(ry, ry, rz * rz));
    return sqrtf(fmaxf(ikey_score(ik) + p2, 0.0f));
}

// First j in [0,8) of the winning group-of-8 with score <= best. The scalar
// chain (incl. h recompute) is bitwise-identical to the packed lanes.
__device__ __forceinline__ int resolve8(const float* __restrict__ xs,
                                        const float* __restrict__ ys,
                                        const float* __restrict__ zs,
                                        float ax, float ay, float az, float best) {
    int r = 7;
#pragma unroll
    for (int j = 6; j >= 0; j--) {
        const float x = xs[j], y = ys[j], z = zs[j];
        const float h = fmaf(x, x, fmaf(y, y, z * z));
        const float s = fmaf(ax, x, fmaf(ay, y, fmaf(az, z, h)));
        if (s <= best) r = j;
    }
    return r;
}

// ITER==1: points = pred, keys -> g_ikey1, partial maxes -> g_rmax1.
// ITER==2: points = refined1 (computed in prologue, half 0 stores to g_ref1),
//          keys -> g_ikey2, partial maxes -> g_rmax2.
template <int ITER>
__global__ __launch_bounds__(NTHREADS, 1)
void scan_kernel(const float* __restrict__ pred,
                 const float* __restrict__ partial) {
    __shared__ float4 sX[NG4H], sY[NG4H], sZ[NG4H];   // 12 KB, SoA-by-4, no H
    __shared__ float s_wmax[NTHREADS / 32];
    __shared__ int s_second;

    const int half = blockIdx.x >> 3;
    const int pblk = blockIdx.x & (HBLK - 1);
    const int b    = blockIdx.y;

    const float* __restrict__ ppb = partial + (size_t)b * NCAND * 3;
    const float4* __restrict__ pp4 = (const float4*)(ppb + (size_t)half * NCH * 3);

    // Transpose load: 3 float4 AoS -> X,Y,Z float4 per group-of-4.
    for (int g = threadIdx.x; g < NG4H; g += NTHREADS) {
        float4 A = pp4[3 * g + 0];   // x0 y0 z0 x1
        float4 B = pp4[3 * g + 1];   // y1 z1 x2 y2
        float4 C = pp4[3 * g + 2];   // z2 x3 y3 z3
        sX[g] = make_float4(A.x, A.w, B.z, C.y);
        sY[g] = make_float4(A.y, B.x, B.w, C.z);
        sZ[g] = make_float4(A.z, B.y, C.x, C.w);
    }
    __syncthreads();

    int   pidx[PPT];
    float rx[PPT], ry[PPT], rz[PPT];
#pragma unroll
    for (int k = 0; k < PPT; k++)
        pidx[k] = pblk * PTS_PER_BLOCK + k * NTHREADS + threadIdx.x;

    if (ITER == 1) {
#pragma unroll
        for (int k = 0; k < PPT; k++) {
            const float* pb = pred + ((size_t)b * NPTS + pidx[k]) * 3;
            rx[k] = pb[0]; ry[k] = pb[1]; rz[k] = pb[2];
        }
    } else {
        // Compute refined1 = update1(pred) from merged iter-1 keys.
        const float rbm1 = 1.0f / (max8(g_rmax1 + b * HBLK) + EPS_F);
#pragma unroll
        for (int k = 0; k < PPT; k++) {
            const size_t base = (size_t)b * NPTS + pidx[k];
            const float* pb = pred + base * 3;
            float x = pb[0], y = pb[1], z = pb[2];
            const ull ik = g_ikey1[base];
            const float d = dist_from_ikey(ik, x, y, z);
            const float a = BASE_ALPHA * (2.0f - d * rbm1);
            const float* pc = ppb + 3 * ikey_idx(ik);
            x += a * (pc[0] - x);
            y += a * (pc[1] - y);
            z += a * (pc[2] - z);
            rx[k] = x; ry[k] = y; rz[k] = z;
            if (half == 0) {               // one copy is enough (values identical)
                float* po = g_ref1 + base * 3;
                po[0] = x; po[1] = y; po[2] = z;
            }
        }
    }

    // Packed broadcast coefficients: a = -2p  (score = a.c + |c|^2).
    ull ax[PPT], ay[PPT], az[PPT];
    float best[PPT];
    int gbest[PPT];
#pragma unroll
    for (int k = 0; k < PPT; k++) {
        ax[k] = pack2(-2.0f * rx[k], -2.0f * rx[k]);
        ay[k] = pack2(-2.0f * ry[k], -2.0f * ry[k]);
        az[k] = pack2(-2.0f * rz[k], -2.0f * rz[k]);
        best[k] = 3.0e38f;
        gbest[k] = 0;
    }

    const ulonglong2* __restrict__ uX = (const ulonglong2*)sX;
    const ulonglong2* __restrict__ uY = (const ulonglong2*)sY;
    const ulonglong2* __restrict__ uZ = (const ulonglong2*)sZ;

    for (int g = 0; g < NG8H; g++) {
        // 6 LDS.128 per group-of-8 candidates
        ulonglong2 Xa = uX[2 * g], Xb = uX[2 * g + 1];
        ulonglong2 Ya = uY[2 * g], Yb = uY[2 * g + 1];
        ulonglong2 Za = uZ[2 * g], Zb = uZ[2 * g + 1];

        // h = x*x + (y*y + z*z), packed, shared across all PPT points
        ull hal = ffma2(Xa.x, Xa.x, ffma2(Ya.x, Ya.x, fmul2(Za.x, Za.x)));
        ull hah = ffma2(Xa.y, Xa.y, ffma2(Ya.y, Ya.y, fmul2(Za.y, Za.y)));
        ull hbl = ffma2(Xb.x, Xb.x, ffma2(Yb.x, Yb.x, fmul2(Zb.x, Zb.x)));
        ull hbh = ffma2(Xb.y, Xb.y, ffma2(Yb.y, Yb.y, fmul2(Zb.y, Zb.y)));

#pragma unroll
        for (int k = 0; k < PPT; k++) {
            ull t0 = ffma2(ax[k], Xa.x, ffma2(ay[k], Ya.x, ffma2(az[k], Za.x, hal)));
            ull t1 = ffma2(ax[k], Xa.y, ffma2(ay[k], Ya.y, ffma2(az[k], Za.y, hah)));
            ull t2 = ffma2(ax[k], Xb.x, ffma2(ay[k], Yb.x, ffma2(az[k], Zb.x, hbl)));
            ull t3 = ffma2(ax[k], Xb.y, ffma2(ay[k], Yb.y, ffma2(az[k], Zb.y, hbh)));
            float s0, s1, s2, s3, s4, s5, s6, s7;
            unpack2(t0, s0, s1);
            unpack2(t1, s2, s3);
            unpack2(t2, s4, s5);
            unpack2(t3, s6, s7);
            float m = fminf(fminf(fminf(s0, s1), fminf(s2, s3)),
                            fminf(fminf(s4, s5), fminf(s6, s7)));
            if (m < best[k]) { best[k] = m; gbest[k] = g; }  // strict <: first wins
        }
    }

    // Publish inverted keys via atomicMax (merged min across halves).
    ull* __restrict__ ikey = (ITER == 1) ? g_ikey1 : g_ikey2;
    const float* fX = (const float*)sX;
    const float* fY = (const float*)sY;
    const float* fZ = (const float*)sZ;
#pragma unroll
    for (int k = 0; k < PPT; k++) {
        const int gq = 8 * gbest[k];
        const int ci = half * NCH + gq +
                       resolve8(fX + gq, fY + gq, fZ + gq,
                                -2.0f * rx[k], -2.0f * ry[k], -2.0f * rz[k], best[k]);
        atomicMax(&ikey[(size_t)b * NPTS + pidx[k]], make_ikey(best[k], ci));
    }
    __threadfence();   // release key writes before counter increment

    // Second finisher of this (b, pblk) pair computes the merged block max.
    unsigned* __restrict__ cnt  = ((ITER == 1) ? g_c1 : g_c2) + b * HBLK + pblk;
    float*    __restrict__ rmax = ((ITER == 1) ? g_rmax1 : g_rmax2) + b * HBLK + pblk;
    if (threadIdx.x == 0) {
        unsigned t = atomicAdd(cnt, 1u);
        s_second = (t == 1);
        if (t == 1) *cnt = 0u;          // reset for the next graph replay
    }
    __syncthreads();
    if (s_second) {
        __threadfence();                 // acquire the other half's key writes
        float mx = 0.0f;
#pragma unroll
        for (int k = 0; k < PPT; k++) {
            const ull ik = ikey[(size_t)b * NPTS + pidx[k]];
            mx = fmaxf(mx, dist_from_ikey(ik, rx[k], ry[k], rz[k]));
        }
#pragma unroll
        for (int off = 16; off > 0; off >>= 1)
            mx = fmaxf(mx, __shfl_xor_sync(0xffffffffu, mx, off));
        if ((threadIdx.x & 31) == 0) s_wmax[threadIdx.x >> 5] = mx;
        __syncthreads();
        if (threadIdx.x == 0) {
            float mm = s_wmax[0];
#pragma unroll
            for (int w = 1; w < NTHREADS / 32; w++) mm = fmaxf(mm, s_wmax[w]);
            *rmax = mm;
        }
    }
}

// refined1 (stored) -> apply update 2 -> out.  256 blocks, 1 pt/thread.
__global__ __launch_bounds__(NTHREADS)
void finalize_kernel(const float* __restrict__ partial,
                     float* __restrict__ out) {
    const int i = blockIdx.x * NTHREADS + threadIdx.x;   // global point index
    if (i >= NBATCH * NPTS) return;
    const int b = i / NPTS;
    const float* __restrict__ ppb = partial + (size_t)b * NCAND * 3;

    float rx = g_ref1[3 * i], ry = g_ref1[3 * i + 1], rz = g_ref1[3 * i + 2];

    const float rbm2 = 1.0f / (max8(g_rmax2 + b * HBLK) + EPS_F);
    const ull ik = g_ikey2[i];
    const float d = dist_from_ikey(ik, rx, ry, rz);
    const float a = BASE_ALPHA * (2.0f - d * rbm2);
    const float* pc = ppb + 3 * ikey_idx(ik);
    rx += a * (pc[0] - rx);
    ry += a * (pc[1] - ry);
    rz += a * (pc[2] - rz);

    out[3 * i + 0] = rx;
    out[3 * i + 1] = ry;
    out[3 * i + 2] = rz;
}

extern "C" void kernel_launch(void* const* d_in, const int* in_sizes, int n_in,
                              void* d_out, int out_size) {
    const float* pred    = (const float*)d_in[0];   // [8,8192,3]
    const float* partial = (const float*)d_in[1];   // [8,2048,3]
    float* out = (float*)d_out;                     // [8,8192,3]

    const dim3 sgrid(NHALF * HBLK, NBATCH);         // 128 scan blocks, 1/SM
    const int  fgrid = (NBATCH * NPTS + NTHREADS - 1) / NTHREADS;  // 256

    scan_kernel<1><<<sgrid, NTHREADS>>>(pred, partial);
    scan_kernel<2><<<sgrid, NTHREADS>>>(pred, partial);
    finalize_kernel<<<fgrid, NTHREADS>>>(partial, out);
}